// round 14
// baseline (speedup 1.0000x reference)
#include <cuda_runtime.h>
#include <cuda_fp16.h>
#include <cstdint>
#include <math.h>

#define SEQ    2048
#define BATCH  2
#define HIDDEN 2048
#define NH     16
#define NKV    4
#define HD     128
#define ROWS   (BATCH*SEQ)   /* 4096 */
#define QDIM   (NH*HD)       /* 2048 */
#define KVDIM  (NKV*HD)      /* 512  */

// ---------------- scratch (device globals: no allocation allowed) ----------
__device__ __half g_xh[ROWS*HIDDEN];    // 16 MB
__device__ __half g_wqh[HIDDEN*QDIM];   //  8 MB
__device__ __half g_wkh[HIDDEN*KVDIM];  //  2 MB
__device__ __half g_wvh[HIDDEN*KVDIM];  //  2 MB
__device__ __half g_woh[QDIM*HIDDEN];   //  8 MB
__device__ __half g_qh[ROWS*QDIM];      // 16 MB
__device__ __half g_kh[ROWS*KVDIM];     //  4 MB
__device__ __half g_vh[ROWS*KVDIM];     //  4 MB
__device__ __half g_ah[ROWS*QDIM];      // 16 MB
__device__ float  g_cos[SEQ*64];
__device__ float  g_sin[SEQ*64];

// ---------------- asm helpers ----------------------------------------------
__device__ __forceinline__ void ldsm4(unsigned* r, const void* p) {
    unsigned a = (unsigned)__cvta_generic_to_shared(p);
    asm volatile("ldmatrix.sync.aligned.m8n8.x4.shared.b16 {%0,%1,%2,%3}, [%4];"
        : "=r"(r[0]), "=r"(r[1]), "=r"(r[2]), "=r"(r[3]) : "r"(a));
}
__device__ __forceinline__ void ldsm4t(unsigned* r, const void* p) {
    unsigned a = (unsigned)__cvta_generic_to_shared(p);
    asm volatile("ldmatrix.sync.aligned.m8n8.x4.trans.shared.b16 {%0,%1,%2,%3}, [%4];"
        : "=r"(r[0]), "=r"(r[1]), "=r"(r[2]), "=r"(r[3]) : "r"(a));
}
__device__ __forceinline__ void mma16(float* d, const unsigned* a,
                                      unsigned b0, unsigned b1) {
    asm volatile("mma.sync.aligned.m16n8k16.row.col.f32.f16.f16.f32 "
        "{%0,%1,%2,%3}, {%4,%5,%6,%7}, {%8,%9}, {%0,%1,%2,%3};"
        : "+f"(d[0]), "+f"(d[1]), "+f"(d[2]), "+f"(d[3])
        : "r"(a[0]), "r"(a[1]), "r"(a[2]), "r"(a[3]), "r"(b0), "r"(b1));
}
__device__ __forceinline__ void cpa16(const void* smem, const void* g) {
    unsigned s = (unsigned)__cvta_generic_to_shared(smem);
    asm volatile("cp.async.cg.shared.global [%0], [%1], 16;" :: "r"(s), "l"(g));
}
__device__ __forceinline__ void cpa16_ca(const void* smem, const void* g) {
    unsigned s = (unsigned)__cvta_generic_to_shared(smem);
    asm volatile("cp.async.ca.shared.global [%0], [%1], 16;" :: "r"(s), "l"(g));
}
__device__ __forceinline__ void cpcommit() { asm volatile("cp.async.commit_group;"); }
template<int N> __device__ __forceinline__ void cpwait() {
    asm volatile("cp.async.wait_group %0;" :: "n"(N));
}
__device__ __forceinline__ unsigned packh2(float x, float y) {
    unsigned r;
    asm("cvt.rn.f16x2.f32 %0, %1, %2;" : "=r"(r) : "f"(y), "f"(x));
    return r;
}

// ---------------- fused fp32 -> fp16 convert + RoPE table (1 launch) -------
#define F2H_BX  8192
#define F2H_BQ  (F2H_BX + 4096)    /* 12288 */
#define F2H_BK  (F2H_BQ + 1024)    /* 13312 */
#define F2H_BV  (F2H_BK + 1024)    /* 14336 */
#define F2H_BO  (F2H_BV + 4096)    /* 18432 */
#define F2H_TOT (F2H_BO + 512)     /* 18944 (last 512 blocks: rope table) */

__global__ void f2h_all(const float4* __restrict__ x,  __half2* __restrict__ xh,
                        const float4* __restrict__ wq, __half2* __restrict__ wqh,
                        const float4* __restrict__ wk, __half2* __restrict__ wkh,
                        const float4* __restrict__ wv, __half2* __restrict__ wvh,
                        const float4* __restrict__ wo, __half2* __restrict__ woh)
{
    int bx = blockIdx.x;
    if (bx >= F2H_BO) {
        // RoPE table (fp32 path, no fp64 transcendentals)
        int i = (bx - F2H_BO) * 256 + threadIdx.x;
        if (i >= SEQ*64) return;
        int s = i >> 6, d = i & 63;
        double base_pow[6] = { 8.6596432336006535e-1, 7.4989420933245583e-1,
                               5.6234132519034908e-1, 3.1622776601683794e-1,
                               1.0e-1, 1.0e-2 };
        double invf = 1.0;
        #pragma unroll
        for (int b = 0; b < 6; b++)
            if (d & (1 << b)) invf *= base_pow[b];
        double ang = (double)s * invf;
        const double TWO_PI_HI = 6.2831853071795862e+0;
        const double TWO_PI_LO = 2.4492935982947064e-16;
        double k = rint(ang * 1.5915494309189533e-1);
        double r = fma(-k, TWO_PI_HI, ang);
        r = fma(-k, TWO_PI_LO, r);
        float sn, cs;
        sincosf((float)r, &sn, &cs);
        g_cos[i] = cs;
        g_sin[i] = sn;
        return;
    }
    const float4* src; __half2* dst; int base;
    if      (bx < F2H_BX) { src = x;  dst = xh;  base = 0; }
    else if (bx < F2H_BQ) { src = wq; dst = wqh; base = F2H_BX; }
    else if (bx < F2H_BK) { src = wk; dst = wkh; base = F2H_BQ; }
    else if (bx < F2H_BV) { src = wv; dst = wvh; base = F2H_BK; }
    else                  { src = wo; dst = woh; base = F2H_BV; }
    int i = (bx - base) * 256 + threadIdx.x;
    float4 v = src[i];
    dst[2*i]   = __floats2half2_rn(v.x, v.y);
    dst[2*i+1] = __floats2half2_rn(v.z, v.w);
}

// ---------------- fused QKV projection + RoPE (HMMA, 2-stage) --------------
#define AST 40
#define BST 136
#define CST 136
#define PROJ_SMEM (2*128*AST*2 + 2*32*BST*2)   /* 37888 bytes */

__global__ __launch_bounds__(256, 2) void proj_qkv(
    const __half* __restrict__ A,
    const __half* __restrict__ Wq, const __half* __restrict__ Wk,
    const __half* __restrict__ Wv,
    __half* __restrict__ Qo, __half* __restrict__ Ko, __half* __restrict__ Vo)
{
    __shared__ __align__(16) char smraw[PROJ_SMEM];
    __half* As = (__half*)smraw;
    __half* Bs = (__half*)(smraw + 2*128*AST*2);
    __half* Cs = (__half*)smraw;

    const int tid  = threadIdx.x;
    const int l    = tid & 31, warp = tid >> 5;
    const int wm = warp >> 2, wn = warp & 3;
    const int bx = blockIdx.x, by = blockIdx.y;
    const int lq = l >> 2, lr = l & 3;

    const __half* Bb; __half* Cb; int ldB; bool rope;
    if (bx < 16)      { Bb = Wq + bx*128;      ldB = QDIM;  Cb = Qo + bx*128;      rope = true; }
    else if (bx < 20) { Bb = Wk + (bx-16)*128; ldB = KVDIM; Cb = Ko + (bx-16)*128; rope = true; }
    else              { Bb = Wv + (bx-20)*128; ldB = KVDIM; Cb = Vo + (bx-20)*128; rope = false; }

    const __half* Ab = A + (size_t)(by*128)*HIDDEN;

    float acc[4][4][4];
    #pragma unroll
    for (int i = 0; i < 4; i++)
        #pragma unroll
        for (int j = 0; j < 4; j++)
            #pragma unroll
            for (int t = 0; t < 4; t++) acc[i][j][t] = 0.f;

    // A loads: .ca (co-resident CTA shares by -> same A tile, L1 reuse)
    #define LOAD_STAGE(buf, k0) do {                                            \
        _Pragma("unroll")                                                       \
        for (int i = 0; i < 2; i++) {                                           \
            int c = tid + i*256;                                                \
            int m = c >> 2, kc = (c & 3) * 8;                                   \
            cpa16_ca(&As[(buf)*128*AST + m*AST + kc], Ab + (size_t)m*HIDDEN + (k0) + kc); \
        }                                                                       \
        _Pragma("unroll")                                                       \
        for (int i = 0; i < 2; i++) {                                           \
            int c = tid + i*256;                                                \
            int k = c >> 4, nc = (c & 15) * 8;                                  \
            cpa16(&Bs[(buf)*32*BST + k*BST + nc], Bb + (size_t)((k0)+k)*ldB + nc); \
        }                                                                       \
        cpcommit();                                                             \
    } while (0)

    LOAD_STAGE(0, 0);

    const int nIter = HIDDEN / 32;
    for (int it = 0; it < nIter; it++) {
        int buf = it & 1;
        if (it + 1 < nIter) { LOAD_STAGE(buf ^ 1, (it+1)*32); cpwait<1>(); }
        else                { cpwait<0>(); }
        __syncthreads();

        #pragma unroll
        for (int kk = 0; kk < 32; kk += 16) {
            unsigned a[4][4], b[2][4];
            #pragma unroll
            for (int mt = 0; mt < 4; mt++) {
                int m0 = wm*64 + mt*16;
                ldsm4(a[mt], &As[buf*128*AST + (m0 + (l & 15))*AST + kk + ((l >> 4) << 3)]);
            }
            #pragma unroll
            for (int g = 0; g < 2; g++) {
                int n0 = wn*32 + g*16;
                ldsm4t(b[g], &Bs[buf*32*BST + (kk + (l & 15))*BST + n0 + ((l >> 4) << 3)]);
            }
            #pragma unroll
            for (int mt = 0; mt < 4; mt++)
                #pragma unroll
                for (int nt = 0; nt < 4; nt++) {
                    const unsigned* bg = b[nt >> 1];
                    if (nt & 1) mma16(acc[mt][nt], a[mt], bg[2], bg[3]);
                    else        mma16(acc[mt][nt], a[mt], bg[0], bg[1]);
                }
        }
        __syncthreads();
    }

    if (!rope) {
        #pragma unroll
        for (int mt = 0; mt < 4; mt++) {
            int row = by*128 + wm*64 + mt*16 + lq;
            #pragma unroll
            for (int nt = 0; nt < 4; nt++) {
                int col = wn*32 + nt*8 + lr*2;
                *(__half2*)&Cb[(size_t) row     *KVDIM + col] =
                    __floats2half2_rn(acc[mt][nt][0], acc[mt][nt][1]);
                *(__half2*)&Cb[(size_t)(row + 8)*KVDIM + col] =
                    __floats2half2_rn(acc[mt][nt][2], acc[mt][nt][3]);
            }
        }
        return;
    }

    const int ldC = (bx < 16) ? QDIM : KVDIM;
    #pragma unroll
    for (int mt = 0; mt < 4; mt++) {
        int row = wm*64 + mt*16 + lq;
        #pragma unroll
        for (int nt = 0; nt < 4; nt++) {
            int col = wn*32 + nt*8 + lr*2;
            *(__half2*)&Cs[ row     *CST + col] =
                __floats2half2_rn(acc[mt][nt][0], acc[mt][nt][1]);
            *(__half2*)&Cs[(row + 8)*CST + col] =
                __floats2half2_rn(acc[mt][nt][2], acc[mt][nt][3]);
        }
    }
    __syncthreads();

    #pragma unroll
    for (int i = 0; i < 32; i++) {
        int e   = tid + i*256;
        int row = e >> 6;
        int c2  = (e & 63) * 2;
        int d   = c2 & 63;
        float2 x1 = __half22float2(*(__half2*)&Cs[row*CST + c2]);
        float2 x2 = __half22float2(*(__half2*)&Cs[row*CST + (c2 ^ 64)]);
        int sp = (by*128 + row) & (SEQ - 1);
        float c0 = g_cos[sp*64 + d],     s0 = g_sin[sp*64 + d];
        float c1 = g_cos[sp*64 + d + 1], s1 = g_sin[sp*64 + d + 1];
        float r0, r1;
        if (c2 < 64) { r0 = x1.x*c0 - x2.x*s0; r1 = x1.y*c1 - x2.y*s1; }
        else         { r0 = x1.x*c0 + x2.x*s0; r1 = x1.y*c1 + x2.y*s1; }
        *(__half2*)&Cb[(size_t)(by*128 + row)*ldC + c2] = __floats2half2_rn(r0, r1);
    }
    #undef LOAD_STAGE
}

// ---------------- Wo GEMM (fp32 out, HMMA, 2-stage) ------------------------
__global__ __launch_bounds__(256, 2) void gemm_f16_f32out(
    const __half* __restrict__ A, const __half* __restrict__ B,
    float* __restrict__ C, int M, int N, int K)
{
    __shared__ __half As[2][128*AST];
    __shared__ __half Bs[2][32*BST];

    const int tid  = threadIdx.x;
    const int l    = tid & 31, warp = tid >> 5;
    const int wm = warp >> 2, wn = warp & 3;
    const int bx = blockIdx.x, by = blockIdx.y;
    const int lq = l >> 2, lr = l & 3;

    const __half* Ab = A + (size_t)(by*128)*K;
    const __half* Bb = B + (size_t)bx*128;

    float acc[4][4][4];
    #pragma unroll
    for (int i = 0; i < 4; i++)
        #pragma unroll
        for (int j = 0; j < 4; j++)
            #pragma unroll
            for (int t = 0; t < 4; t++) acc[i][j][t] = 0.f;

    #define LOAD_STAGE(buf, k0) do {                                           \
        _Pragma("unroll")                                                      \
        for (int i = 0; i < 2; i++) {                                          \
            int c = tid + i*256;                                               \
            int m = c >> 2, kc = (c & 3) * 8;                                  \
            cpa16_ca(&As[buf][m*AST + kc], Ab + (size_t)m*K + (k0) + kc);      \
        }                                                                      \
        _Pragma("unroll")                                                      \
        for (int i = 0; i < 2; i++) {                                          \
            int c = tid + i*256;                                               \
            int k = c >> 4, nc = (c & 15) * 8;                                 \
            cpa16(&Bs[buf][k*BST + nc], Bb + (size_t)((k0)+k)*N + nc);         \
        }                                                                      \
        cpcommit();                                                            \
    } while (0)

    LOAD_STAGE(0, 0);

    const int nIter = K / 32;
    for (int it = 0; it < nIter; it++) {
        int buf = it & 1;
        if (it + 1 < nIter) { LOAD_STAGE(buf ^ 1, (it+1)*32); cpwait<1>(); }
        else                { cpwait<0>(); }
        __syncthreads();

        #pragma unroll
        for (int kk = 0; kk < 32; kk += 16) {
            unsigned a[4][4], b[2][4];
            #pragma unroll
            for (int mt = 0; mt < 4; mt++) {
                int m0 = wm*64 + mt*16;
                ldsm4(a[mt], &As[buf][(m0 + (l & 15))*AST + kk + ((l >> 4) << 3)]);
            }
            #pragma unroll
            for (int g = 0; g < 2; g++) {
                int n0 = wn*32 + g*16;
                ldsm4t(b[g], &Bs[buf][(kk + (l & 15))*BST + n0 + ((l >> 4) << 3)]);
            }
            #pragma unroll
            for (int mt = 0; mt < 4; mt++)
                #pragma unroll
                for (int nt = 0; nt < 4; nt++) {
                    const unsigned* bg = b[nt >> 1];
                    if (nt & 1) mma16(acc[mt][nt], a[mt], bg[2], bg[3]);
                    else        mma16(acc[mt][nt], a[mt], bg[0], bg[1]);
                }
        }
        __syncthreads();
    }

    #pragma unroll
    for (int mt = 0; mt < 4; mt++) {
        int row = by*128 + wm*64 + mt*16 + lq;
        #pragma unroll
        for (int nt = 0; nt < 4; nt++) {
            int col = bx*128 + wn*32 + nt*8 + lr*2;
            *(float2*)&C[(size_t) row     *N + col] =
                make_float2(acc[mt][nt][0], acc[mt][nt][1]);
            *(float2*)&C[(size_t)(row + 8)*N + col] =
                make_float2(acc[mt][nt][2], acc[mt][nt][3]);
        }
    }
    #undef LOAD_STAGE
}

// ---------------- flash attention: BM=64, BN=128, P in regs ----------------
#define QST 136
#define KST 136
#define VST 136
#define QS_OFF 0
#define KS_OFF (64*QST)                /* 8704  */
#define VS_OFF (KS_OFF + 128*KST)      /* 26112 */
#define FLASH_SMEM ((VS_OFF + 128*VST)*2)   /* 87040 bytes */

__global__ __launch_bounds__(128, 2) void flash_f16(
    const __half* __restrict__ Q, const __half* __restrict__ K,
    const __half* __restrict__ V, __half* __restrict__ O)
{
    extern __shared__ __half sh[];
    const int tid  = threadIdx.x;
    const int l    = tid & 31, w = tid >> 5;
    const int lq = l >> 2, lr = l & 3;
    const int qt = (gridDim.x - 1) - blockIdx.x;   // heavy tiles first
    const int h  = blockIdx.y, b = blockIdx.z;
    const int hk = h >> 2;
    const int q0 = qt * 64;
    const float sc2 = 0.08838834764831845f * 1.4426950408889634f;

    const __half* Qbase = Q + (size_t)(b*SEQ + q0)*QDIM + h*128;
    const __half* Kb0   = K + (size_t)(b*SEQ)*KVDIM + hk*128;
    const __half* Vb0   = V + (size_t)(b*SEQ)*KVDIM + hk*128;

    #pragma unroll
    for (int i = 0; i < 8; i++) {
        int c = tid + i*128;
        int m = c >> 4, kc = (c & 15) * 8;
        cpa16(&sh[QS_OFF + m*QST + kc], Qbase + (size_t)m*QDIM + kc);
    }
    cpcommit();

    #define LOAD_K(kt) do {                                                    \
        const __half* kb = Kb0 + (size_t)(kt)*128*KVDIM;                       \
        _Pragma("unroll")                                                      \
        for (int i = 0; i < 16; i++) {                                         \
            int c = tid + i*128;                                               \
            int r = c >> 4, kc = (c & 15) * 8;                                 \
            cpa16(&sh[KS_OFF + r*KST + kc], kb + (size_t)r*KVDIM + kc);        \
        }                                                                      \
        cpcommit();                                                            \
    } while (0)
    #define LOAD_V(kt) do {                                                    \
        const __half* vb = Vb0 + (size_t)(kt)*128*KVDIM;                       \
        _Pragma("unroll")                                                      \
        for (int i = 0; i < 16; i++) {                                         \
            int c = tid + i*128;                                               \
            int r = c >> 4, kc = (c & 15) * 8;                                 \
            cpa16(&sh[VS_OFF + r*VST + kc], vb + (size_t)r*KVDIM + kc);        \
        }                                                                      \
        cpcommit();                                                            \
    } while (0)

    LOAD_K(0);
    LOAD_V(0);

    float o[16][4];
    #pragma unroll
    for (int nt = 0; nt < 16; nt++)
        #pragma unroll
        for (int t = 0; t < 4; t++) o[nt][t] = 0.f;
    float m0 = -INFINITY, m1 = -INFINITY, l0 = 0.f, l1 = 0.f;

    const int nkt  = qt/2 + 1;
    const int mrow = w*16 + lq;
    const int lidx = l & 15, lhi = (l >> 4) << 3;

    for (int kt = 0; kt < nkt; kt++) {
        cpwait<1>();
        __syncthreads();

        float s[16][4];
        #pragma unroll
        for (int nt = 0; nt < 16; nt++)
            #pragma unroll
            for (int t = 0; t < 4; t++) s[nt][t] = 0.f;

        #pragma unroll
        for (int kk = 0; kk < 128; kk += 16) {
            unsigned a[4];
            ldsm4(a, &sh[QS_OFF + (w*16 + lidx)*QST + kk + lhi]);
            #pragma unroll
            for (int g = 0; g < 8; g++) {
                unsigned bk[4];
                int n0 = g*16;
                ldsm4(bk, &sh[KS_OFF + (n0 + ((l >> 4) << 3) + (l & 7))*KST
                               + kk + (((l >> 3) & 1) << 3)]);
                mma16(s[g*2],     a, bk[0], bk[1]);
                mma16(s[g*2 + 1], a, bk[2], bk[3]);
            }
        }

        const int r0 = q0 + mrow, r1 = r0 + 8;
        const bool need_mask = (kt == nkt - 1);
        #pragma unroll
        for (int nt = 0; nt < 16; nt++) {
            int col = kt*128 + nt*8 + lr*2;
            s[nt][0] *= sc2; s[nt][1] *= sc2;
            s[nt][2] *= sc2; s[nt][3] *= sc2;
            if (need_mask) {
                if (col     > r0) s[nt][0] = -INFINITY;
                if (col + 1 > r0) s[nt][1] = -INFINITY;
                if (col     > r1) s[nt][2] = -INFINITY;
                if (col + 1 > r1) s[nt][3] = -INFINITY;
            }
        }

        float mx0 = -INFINITY, mx1 = -INFINITY;
        #pragma unroll
        for (int nt = 0; nt < 16; nt++) {
            mx0 = fmaxf(mx0, fmaxf(s[nt][0], s[nt][1]));
            mx1 = fmaxf(mx1, fmaxf(s[nt][2], s[nt][3]));
        }
        mx0 = fmaxf(mx0, __shfl_xor_sync(0xffffffffu, mx0, 1));
        mx0 = fmaxf(mx0, __shfl_xor_sync(0xffffffffu, mx0, 2));
        mx1 = fmaxf(mx1, __shfl_xor_sync(0xffffffffu, mx1, 1));
        mx1 = fmaxf(mx1, __shfl_xor_sync(0xffffffffu, mx1, 2));
        float mn0 = fmaxf(m0, mx0), mn1 = fmaxf(m1, mx1);
        float al0 = exp2f(m0 - mn0), al1 = exp2f(m1 - mn1);

        unsigned aP[8][4];
        float rs0 = 0.f, rs1 = 0.f;
        #pragma unroll
        for (int nt = 0; nt < 16; nt++) {
            float p0 = exp2f(s[nt][0] - mn0);
            float p1 = exp2f(s[nt][1] - mn0);
            float p2 = exp2f(s[nt][2] - mn1);
            float p3 = exp2f(s[nt][3] - mn1);
            rs0 += p0 + p1; rs1 += p2 + p3;
            int g = nt >> 1;
            if (nt & 1) {
                aP[g][2] = packh2(p0, p1);
                aP[g][3] = packh2(p2, p3);
            } else {
                aP[g][0] = packh2(p0, p1);
                aP[g][1] = packh2(p2, p3);
            }
        }
        rs0 += __shfl_xor_sync(0xffffffffu, rs0, 1);
        rs0 += __shfl_xor_sync(0xffffffffu, rs0, 2);
        rs1 += __shfl_xor_sync(0xffffffffu, rs1, 1);
        rs1 += __shfl_xor_sync(0xffffffffu, rs1, 2);
        l0 = l0*al0 + rs0;  l1 = l1*al1 + rs1;
        m0 = mn0;           m1 = mn1;

        if (__ballot_sync(0xffffffffu, (al0 != 1.f) | (al1 != 1.f))) {
            #pragma unroll
            for (int nt = 0; nt < 16; nt++) {
                o[nt][0] *= al0; o[nt][1] *= al0;
                o[nt][2] *= al1; o[nt][3] *= al1;
            }
        }

        cpwait<0>();
        __syncthreads();

        if (kt + 1 < nkt) LOAD_K(kt + 1);

        #pragma unroll
        for (int g4 = 0; g4 < 8; g4++) {
            #pragma unroll
            for (int vg = 0; vg < 8; vg++) {
                unsigned bv[4];
                ldsm4t(bv, &sh[VS_OFF + (g4*16 + lidx)*VST + vg*16 + lhi]);
                mma16(o[vg*2],     aP[g4], bv[0], bv[1]);
                mma16(o[vg*2 + 1], aP[g4], bv[2], bv[3]);
            }
        }

        if (kt + 1 < nkt) {
            __syncthreads();
            LOAD_V(kt + 1);
        }
    }

    float inv0 = 1.f / l0, inv1 = 1.f / l1;
    __half* Ob = O + (size_t)(b*SEQ + q0)*QDIM + h*128;
    #pragma unroll
    for (int nt = 0; nt < 16; nt++) {
        int col = nt*8 + lr*2;
        *(__half2*)&Ob[(size_t) mrow     *QDIM + col] =
            __floats2half2_rn(o[nt][0]*inv0, o[nt][1]*inv0);
        *(__half2*)&Ob[(size_t)(mrow + 8)*QDIM + col] =
            __floats2half2_rn(o[nt][2]*inv1, o[nt][3]*inv1);
    }
    #undef LOAD_K
    #undef LOAD_V
}

// ---------------- launch ---------------------------------------------------
extern "C" void kernel_launch(void* const* d_in, const int* in_sizes, int n_in,
                              void* d_out, int out_size)
{
    const float* x  = (const float*)d_in[0];
    const float* Wq = (const float*)d_in[1];
    const float* Wk = (const float*)d_in[2];
    const float* Wv = (const float*)d_in[3];
    const float* Wo = (const float*)d_in[4];
    float* out = (float*)d_out;

    __half *xh, *wqh, *wkh, *wvh, *woh, *qh, *kh, *vh, *ah;
    cudaGetSymbolAddress((void**)&xh,  g_xh);
    cudaGetSymbolAddress((void**)&wqh, g_wqh);
    cudaGetSymbolAddress((void**)&wkh, g_wkh);
    cudaGetSymbolAddress((void**)&wvh, g_wvh);
    cudaGetSymbolAddress((void**)&woh, g_woh);
    cudaGetSymbolAddress((void**)&qh,  g_qh);
    cudaGetSymbolAddress((void**)&kh,  g_kh);
    cudaGetSymbolAddress((void**)&vh,  g_vh);
    cudaGetSymbolAddress((void**)&ah,  g_ah);

    f2h_all<<<F2H_TOT, 256>>>((const float4*)x,  (__half2*)xh,
                              (const float4*)Wq, (__half2*)wqh,
                              (const float4*)Wk, (__half2*)wkh,
                              (const float4*)Wv, (__half2*)wvh,
                              (const float4*)Wo, (__half2*)woh);

    proj_qkv<<<dim3(24, ROWS/128), 256>>>(xh, wqh, wkh, wvh, qh, kh, vh);

    cudaFuncSetAttribute(flash_f16, cudaFuncAttributeMaxDynamicSharedMemorySize,
                         FLASH_SMEM);
    flash_f16<<<dim3(SEQ/64, NH, BATCH), 128, FLASH_SMEM>>>(qh, kh, vh, ah);

    gemm_f16_f32out<<<dim3(QDIM/128, ROWS/128), 256>>>(ah, woh, out, ROWS, QDIM, HIDDEN);
}

// round 15
// speedup vs baseline: 1.0195x; 1.0195x over previous
#include <cuda_runtime.h>
#include <cuda_fp16.h>
#include <cstdint>
#include <math.h>

#define SEQ    2048
#define BATCH  2
#define HIDDEN 2048
#define NH     16
#define NKV    4
#define HD     128
#define ROWS   (BATCH*SEQ)   /* 4096 */
#define QDIM   (NH*HD)       /* 2048 */
#define KVDIM  (NKV*HD)      /* 512  */

// ---------------- scratch (device globals: no allocation allowed) ----------
__device__ __half g_xh[ROWS*HIDDEN];    // 16 MB
__device__ __half g_wqh[HIDDEN*QDIM];   //  8 MB
__device__ __half g_wkh[HIDDEN*KVDIM];  //  2 MB
__device__ __half g_wvh[HIDDEN*KVDIM];  //  2 MB
__device__ __half g_woh[QDIM*HIDDEN];   //  8 MB
__device__ __half g_qh[ROWS*QDIM];      // 16 MB
__device__ __half g_kh[ROWS*KVDIM];     //  4 MB
__device__ __half g_vh[ROWS*KVDIM];     //  4 MB
__device__ __half g_ah[ROWS*QDIM];      // 16 MB
__device__ float  g_cos[SEQ*64];
__device__ float  g_sin[SEQ*64];

// ---------------- asm helpers ----------------------------------------------
__device__ __forceinline__ void ldsm4(unsigned* r, const void* p) {
    unsigned a = (unsigned)__cvta_generic_to_shared(p);
    asm volatile("ldmatrix.sync.aligned.m8n8.x4.shared.b16 {%0,%1,%2,%3}, [%4];"
        : "=r"(r[0]), "=r"(r[1]), "=r"(r[2]), "=r"(r[3]) : "r"(a));
}
__device__ __forceinline__ void ldsm4t(unsigned* r, const void* p) {
    unsigned a = (unsigned)__cvta_generic_to_shared(p);
    asm volatile("ldmatrix.sync.aligned.m8n8.x4.trans.shared.b16 {%0,%1,%2,%3}, [%4];"
        : "=r"(r[0]), "=r"(r[1]), "=r"(r[2]), "=r"(r[3]) : "r"(a));
}
__device__ __forceinline__ void mma16(float* d, const unsigned* a,
                                      unsigned b0, unsigned b1) {
    asm volatile("mma.sync.aligned.m16n8k16.row.col.f32.f16.f16.f32 "
        "{%0,%1,%2,%3}, {%4,%5,%6,%7}, {%8,%9}, {%0,%1,%2,%3};"
        : "+f"(d[0]), "+f"(d[1]), "+f"(d[2]), "+f"(d[3])
        : "r"(a[0]), "r"(a[1]), "r"(a[2]), "r"(a[3]), "r"(b0), "r"(b1));
}
__device__ __forceinline__ void cpa16(const void* smem, const void* g) {
    unsigned s = (unsigned)__cvta_generic_to_shared(smem);
    asm volatile("cp.async.cg.shared.global [%0], [%1], 16;" :: "r"(s), "l"(g));
}
__device__ __forceinline__ void cpcommit() { asm volatile("cp.async.commit_group;"); }
template<int N> __device__ __forceinline__ void cpwait() {
    asm volatile("cp.async.wait_group %0;" :: "n"(N));
}
__device__ __forceinline__ unsigned packh2(float x, float y) {
    unsigned r;
    asm("cvt.rn.f16x2.f32 %0, %1, %2;" : "=r"(r) : "f"(y), "f"(x));
    return r;
}

// ---------------- fused fp32 -> fp16 convert (all 5 arrays, 1 launch) ------
#define F2H_BX  8192
#define F2H_BQ  (F2H_BX + 4096)    /* 12288 */
#define F2H_BK  (F2H_BQ + 1024)    /* 13312 */
#define F2H_BV  (F2H_BK + 1024)    /* 14336 */
#define F2H_TOT (F2H_BV + 4096)    /* 18432 */

__global__ void f2h_all(const float4* __restrict__ x,  __half2* __restrict__ xh,
                        const float4* __restrict__ wq, __half2* __restrict__ wqh,
                        const float4* __restrict__ wk, __half2* __restrict__ wkh,
                        const float4* __restrict__ wv, __half2* __restrict__ wvh,
                        const float4* __restrict__ wo, __half2* __restrict__ woh)
{
    int bx = blockIdx.x;
    const float4* src; __half2* dst; int base;
    if      (bx < F2H_BX) { src = x;  dst = xh;  base = 0; }
    else if (bx < F2H_BQ) { src = wq; dst = wqh; base = F2H_BX; }
    else if (bx < F2H_BK) { src = wk; dst = wkh; base = F2H_BQ; }
    else if (bx < F2H_BV) { src = wv; dst = wvh; base = F2H_BK; }
    else                  { src = wo; dst = woh; base = F2H_BV; }
    int i = (bx - base) * 256 + threadIdx.x;
    float4 v = src[i];
    dst[2*i]   = __floats2half2_rn(v.x, v.y);
    dst[2*i+1] = __floats2half2_rn(v.z, v.w);
}

// ---------------- RoPE table (no fp64 transcendentals) ---------------------
__global__ void rope_table_kernel() {
    int i = blockIdx.x * blockDim.x + threadIdx.x;
    if (i >= SEQ*64) return;
    int s = i >> 6, d = i & 63;
    double base_pow[6] = { 8.6596432336006535e-1, 7.4989420933245583e-1,
                           5.6234132519034908e-1, 3.1622776601683794e-1,
                           1.0e-1, 1.0e-2 };
    double invf = 1.0;
    #pragma unroll
    for (int b = 0; b < 6; b++)
        if (d & (1 << b)) invf *= base_pow[b];
    double ang = (double)s * invf;
    const double TWO_PI_HI = 6.2831853071795862e+0;
    const double TWO_PI_LO = 2.4492935982947064e-16;
    double k = rint(ang * 1.5915494309189533e-1);
    double r = fma(-k, TWO_PI_HI, ang);
    r = fma(-k, TWO_PI_LO, r);
    float sn, cs;
    sincosf((float)r, &sn, &cs);
    g_cos[i] = cs;
    g_sin[i] = sn;
}

// ---------------- GEMM tiles: 128x128, BK=64, 2-stage, 256 thr -------------
#define AST2 72     /* A row stride in halves (144 B; 36 words ≡ 4 mod 32) */
#define BST  136    /* B row stride in halves */
#define CST  136
#define ASTAGE (128*AST2)          /* 9216 halves  */
#define BSTAGE (64*BST)            /* 8704 halves  */
#define GSMEM  ((2*ASTAGE + 2*BSTAGE)*2)   /* 71680 bytes */

// A tile: 128 rows x 64 halves = 1024 16B-chunks (m = c>>3, kc = (c&7)*8)
// B tile: 64 rows x 128 halves = 1024 16B-chunks (k = c>>4, nc = (c&15)*8)
#define G_LOAD_STAGE(As, Bs, buf, k0, Ab, ldA, Bb, ldB) do {                   \
    _Pragma("unroll")                                                          \
    for (int i_ = 0; i_ < 4; i_++) {                                           \
        int c_ = tid + i_*256;                                                 \
        int m_ = c_ >> 3, kc_ = (c_ & 7) * 8;                                  \
        cpa16(&As[(buf)*ASTAGE + m_*AST2 + kc_],                               \
              Ab + (size_t)m_*(ldA) + (k0) + kc_);                             \
    }                                                                          \
    _Pragma("unroll")                                                          \
    for (int i_ = 0; i_ < 4; i_++) {                                           \
        int c_ = tid + i_*256;                                                 \
        int k_ = c_ >> 4, nc_ = (c_ & 15) * 8;                                 \
        cpa16(&Bs[(buf)*BSTAGE + k_*BST + nc_],                                \
              Bb + (size_t)((k0)+k_)*(ldB) + nc_);                             \
    }                                                                          \
    cpcommit();                                                                \
} while (0)

#define G_COMPUTE(As, Bs, buf) do {                                            \
    _Pragma("unroll")                                                          \
    for (int kk = 0; kk < 64; kk += 16) {                                      \
        unsigned a_[4][4], b_[2][4];                                           \
        _Pragma("unroll")                                                      \
        for (int mt = 0; mt < 4; mt++) {                                       \
            int m0 = wm*64 + mt*16;                                            \
            ldsm4(a_[mt], &As[(buf)*ASTAGE + (m0 + (l & 15))*AST2 + kk         \
                               + ((l >> 4) << 3)]);                            \
        }                                                                      \
        _Pragma("unroll")                                                      \
        for (int g = 0; g < 2; g++) {                                          \
            int n0 = wn*32 + g*16;                                             \
            ldsm4t(b_[g], &Bs[(buf)*BSTAGE + (kk + (l & 15))*BST + n0          \
                               + ((l >> 4) << 3)]);                            \
        }                                                                      \
        _Pragma("unroll")                                                      \
        for (int mt = 0; mt < 4; mt++)                                         \
            _Pragma("unroll")                                                  \
            for (int nt = 0; nt < 4; nt++) {                                   \
                const unsigned* bg = b_[nt >> 1];                              \
                if (nt & 1) mma16(acc[mt][nt], a_[mt], bg[2], bg[3]);          \
                else        mma16(acc[mt][nt], a_[mt], bg[0], bg[1]);          \
            }                                                                  \
    }                                                                          \
} while (0)

// ---------------- fused QKV projection + RoPE ------------------------------
__global__ __launch_bounds__(256, 2) void proj_qkv(
    const __half* __restrict__ A,
    const __half* __restrict__ Wq, const __half* __restrict__ Wk,
    const __half* __restrict__ Wv,
    __half* __restrict__ Qo, __half* __restrict__ Ko, __half* __restrict__ Vo)
{
    extern __shared__ __half psm[];
    __half* As = psm;                       // [2][ASTAGE]
    __half* Bs = psm + 2*ASTAGE;            // [2][BSTAGE]
    __half* Cs = psm;                       // [128*CST] epilogue alias

    const int tid  = threadIdx.x;
    const int l    = tid & 31, warp = tid >> 5;
    const int wm = warp >> 2, wn = warp & 3;
    const int bx = blockIdx.x, by = blockIdx.y;
    const int lq = l >> 2, lr = l & 3;

    const __half* Bb; __half* Cb; int ldB; bool rope;
    if (bx < 16)      { Bb = Wq + bx*128;      ldB = QDIM;  Cb = Qo + bx*128;      rope = true; }
    else if (bx < 20) { Bb = Wk + (bx-16)*128; ldB = KVDIM; Cb = Ko + (bx-16)*128; rope = true; }
    else              { Bb = Wv + (bx-20)*128; ldB = KVDIM; Cb = Vo + (bx-20)*128; rope = false; }

    const __half* Ab = A + (size_t)(by*128)*HIDDEN;

    float acc[4][4][4];
    #pragma unroll
    for (int i = 0; i < 4; i++)
        #pragma unroll
        for (int j = 0; j < 4; j++)
            #pragma unroll
            for (int t = 0; t < 4; t++) acc[i][j][t] = 0.f;

    G_LOAD_STAGE(As, Bs, 0, 0, Ab, HIDDEN, Bb, ldB);

    const int nIter = HIDDEN / 64;   // 32
    for (int it = 0; it < nIter; it++) {
        int buf = it & 1;
        if (it + 1 < nIter) {
            G_LOAD_STAGE(As, Bs, buf ^ 1, (it+1)*64, Ab, HIDDEN, Bb, ldB);
            cpwait<1>();
        } else cpwait<0>();
        __syncthreads();
        G_COMPUTE(As, Bs, buf);
        __syncthreads();
    }

    if (!rope) {
        #pragma unroll
        for (int mt = 0; mt < 4; mt++) {
            int row = by*128 + wm*64 + mt*16 + lq;
            #pragma unroll
            for (int nt = 0; nt < 4; nt++) {
                int col = wn*32 + nt*8 + lr*2;
                *(__half2*)&Cb[(size_t) row     *KVDIM + col] =
                    __floats2half2_rn(acc[mt][nt][0], acc[mt][nt][1]);
                *(__half2*)&Cb[(size_t)(row + 8)*KVDIM + col] =
                    __floats2half2_rn(acc[mt][nt][2], acc[mt][nt][3]);
            }
        }
        return;
    }

    const int ldC = (bx < 16) ? QDIM : KVDIM;
    #pragma unroll
    for (int mt = 0; mt < 4; mt++) {
        int row = wm*64 + mt*16 + lq;
        #pragma unroll
        for (int nt = 0; nt < 4; nt++) {
            int col = wn*32 + nt*8 + lr*2;
            *(__half2*)&Cs[ row     *CST + col] =
                __floats2half2_rn(acc[mt][nt][0], acc[mt][nt][1]);
            *(__half2*)&Cs[(row + 8)*CST + col] =
                __floats2half2_rn(acc[mt][nt][2], acc[mt][nt][3]);
        }
    }
    __syncthreads();

    #pragma unroll
    for (int i = 0; i < 32; i++) {
        int e   = tid + i*256;
        int row = e >> 6;
        int c2  = (e & 63) * 2;
        int d   = c2 & 63;
        float2 x1 = __half22float2(*(__half2*)&Cs[row*CST + c2]);
        float2 x2 = __half22float2(*(__half2*)&Cs[row*CST + (c2 ^ 64)]);
        int sp = (by*128 + row) & (SEQ - 1);
        float c0 = g_cos[sp*64 + d],     s0 = g_sin[sp*64 + d];
        float c1 = g_cos[sp*64 + d + 1], s1 = g_sin[sp*64 + d + 1];
        float r0, r1;
        if (c2 < 64) { r0 = x1.x*c0 - x2.x*s0; r1 = x1.y*c1 - x2.y*s1; }
        else         { r0 = x1.x*c0 + x2.x*s0; r1 = x1.y*c1 + x2.y*s1; }
        *(__half2*)&Cb[(size_t)(by*128 + row)*ldC + c2] = __floats2half2_rn(r0, r1);
    }
}

// ---------------- Wo GEMM (fp32 out) ---------------------------------------
__global__ __launch_bounds__(256, 2) void gemm_f16_f32out(
    const __half* __restrict__ A, const __half* __restrict__ B,
    float* __restrict__ C, int M, int N, int K)
{
    extern __shared__ __half gsm[];
    __half* As = gsm;
    __half* Bs = gsm + 2*ASTAGE;

    const int tid  = threadIdx.x;
    const int l    = tid & 31, warp = tid >> 5;
    const int wm = warp >> 2, wn = warp & 3;
    const int bx = blockIdx.x, by = blockIdx.y;
    const int lq = l >> 2, lr = l & 3;

    const __half* Ab = A + (size_t)(by*128)*K;
    const __half* Bb = B + (size_t)bx*128;

    float acc[4][4][4];
    #pragma unroll
    for (int i = 0; i < 4; i++)
        #pragma unroll
        for (int j = 0; j < 4; j++)
            #pragma unroll
            for (int t = 0; t < 4; t++) acc[i][j][t] = 0.f;

    G_LOAD_STAGE(As, Bs, 0, 0, Ab, K, Bb, N);

    const int nIter = K / 64;
    for (int it = 0; it < nIter; it++) {
        int buf = it & 1;
        if (it + 1 < nIter) {
            G_LOAD_STAGE(As, Bs, buf ^ 1, (it+1)*64, Ab, K, Bb, N);
            cpwait<1>();
        } else cpwait<0>();
        __syncthreads();
        G_COMPUTE(As, Bs, buf);
        __syncthreads();
    }

    #pragma unroll
    for (int mt = 0; mt < 4; mt++) {
        int row = by*128 + wm*64 + mt*16 + lq;
        #pragma unroll
        for (int nt = 0; nt < 4; nt++) {
            int col = bx*128 + wn*32 + nt*8 + lr*2;
            *(float2*)&C[(size_t) row     *N + col] =
                make_float2(acc[mt][nt][0], acc[mt][nt][1]);
            *(float2*)&C[(size_t)(row + 8)*N + col] =
                make_float2(acc[mt][nt][2], acc[mt][nt][3]);
        }
    }
}

// ---------------- flash attention: BM=64, BN=128, P in regs (R10) ----------
#define QST 136
#define KST 136
#define VST 136
#define QS_OFF 0
#define KS_OFF (64*QST)                /* 8704  */
#define VS_OFF (KS_OFF + 128*KST)      /* 26112 */
#define FLASH_SMEM ((VS_OFF + 128*VST)*2)   /* 87040 bytes */

__global__ __launch_bounds__(128, 2) void flash_f16(
    const __half* __restrict__ Q, const __half* __restrict__ K,
    const __half* __restrict__ V, __half* __restrict__ O)
{
    extern __shared__ __half sh[];
    const int tid  = threadIdx.x;
    const int l    = tid & 31, w = tid >> 5;
    const int lq = l >> 2, lr = l & 3;
    const int qt = (gridDim.x - 1) - blockIdx.x;   // heavy tiles first
    const int h  = blockIdx.y, b = blockIdx.z;
    const int hk = h >> 2;
    const int q0 = qt * 64;
    const float sc2 = 0.08838834764831845f * 1.4426950408889634f;

    const __half* Qbase = Q + (size_t)(b*SEQ + q0)*QDIM + h*128;
    const __half* Kb0   = K + (size_t)(b*SEQ)*KVDIM + hk*128;
    const __half* Vb0   = V + (size_t)(b*SEQ)*KVDIM + hk*128;

    #pragma unroll
    for (int i = 0; i < 8; i++) {
        int c = tid + i*128;
        int m = c >> 4, kc = (c & 15) * 8;
        cpa16(&sh[QS_OFF + m*QST + kc], Qbase + (size_t)m*QDIM + kc);
    }
    cpcommit();

    #define LOAD_K(kt) do {                                                    \
        const __half* kb = Kb0 + (size_t)(kt)*128*KVDIM;                       \
        _Pragma("unroll")                                                      \
        for (int i = 0; i < 16; i++) {                                         \
            int c = tid + i*128;                                               \
            int r = c >> 4, kc = (c & 15) * 8;                                 \
            cpa16(&sh[KS_OFF + r*KST + kc], kb + (size_t)r*KVDIM + kc);        \
        }                                                                      \
        cpcommit();                                                            \
    } while (0)
    #define LOAD_V(kt) do {                                                    \
        const __half* vb = Vb0 + (size_t)(kt)*128*KVDIM;                       \
        _Pragma("unroll")                                                      \
        for (int i = 0; i < 16; i++) {                                         \
            int c = tid + i*128;                                               \
            int r = c >> 4, kc = (c & 15) * 8;                                 \
            cpa16(&sh[VS_OFF + r*VST + kc], vb + (size_t)r*KVDIM + kc);        \
        }                                                                      \
        cpcommit();                                                            \
    } while (0)

    LOAD_K(0);
    LOAD_V(0);

    float o[16][4];
    #pragma unroll
    for (int nt = 0; nt < 16; nt++)
        #pragma unroll
        for (int t = 0; t < 4; t++) o[nt][t] = 0.f;
    float m0 = -INFINITY, m1 = -INFINITY, l0 = 0.f, l1 = 0.f;

    const int nkt  = qt/2 + 1;
    const int mrow = w*16 + lq;
    const int lidx = l & 15, lhi = (l >> 4) << 3;

    for (int kt = 0; kt < nkt; kt++) {
        cpwait<1>();
        __syncthreads();

        float s[16][4];
        #pragma unroll
        for (int nt = 0; nt < 16; nt++)
            #pragma unroll
            for (int t = 0; t < 4; t++) s[nt][t] = 0.f;

        #pragma unroll
        for (int kk = 0; kk < 128; kk += 16) {
            unsigned a[4];
            ldsm4(a, &sh[QS_OFF + (w*16 + lidx)*QST + kk + lhi]);
            #pragma unroll
            for (int g = 0; g < 8; g++) {
                unsigned bk[4];
                int n0 = g*16;
                ldsm4(bk, &sh[KS_OFF + (n0 + ((l >> 4) << 3) + (l & 7))*KST
                               + kk + (((l >> 3) & 1) << 3)]);
                mma16(s[g*2],     a, bk[0], bk[1]);
                mma16(s[g*2 + 1], a, bk[2], bk[3]);
            }
        }

        const int r0 = q0 + mrow, r1 = r0 + 8;
        const bool need_mask = (kt == nkt - 1);
        #pragma unroll
        for (int nt = 0; nt < 16; nt++) {
            int col = kt*128 + nt*8 + lr*2;
            s[nt][0] *= sc2; s[nt][1] *= sc2;
            s[nt][2] *= sc2; s[nt][3] *= sc2;
            if (need_mask) {
                if (col     > r0) s[nt][0] = -INFINITY;
                if (col + 1 > r0) s[nt][1] = -INFINITY;
                if (col     > r1) s[nt][2] = -INFINITY;
                if (col + 1 > r1) s[nt][3] = -INFINITY;
            }
        }

        float mx0 = -INFINITY, mx1 = -INFINITY;
        #pragma unroll
        for (int nt = 0; nt < 16; nt++) {
            mx0 = fmaxf(mx0, fmaxf(s[nt][0], s[nt][1]));
            mx1 = fmaxf(mx1, fmaxf(s[nt][2], s[nt][3]));
        }
        mx0 = fmaxf(mx0, __shfl_xor_sync(0xffffffffu, mx0, 1));
        mx0 = fmaxf(mx0, __shfl_xor_sync(0xffffffffu, mx0, 2));
        mx1 = fmaxf(mx1, __shfl_xor_sync(0xffffffffu, mx1, 1));
        mx1 = fmaxf(mx1, __shfl_xor_sync(0xffffffffu, mx1, 2));
        float mn0 = fmaxf(m0, mx0), mn1 = fmaxf(m1, mx1);
        float al0 = exp2f(m0 - mn0), al1 = exp2f(m1 - mn1);

        unsigned aP[8][4];
        float rs0 = 0.f, rs1 = 0.f;
        #pragma unroll
        for (int nt = 0; nt < 16; nt++) {
            float p0 = exp2f(s[nt][0] - mn0);
            float p1 = exp2f(s[nt][1] - mn0);
            float p2 = exp2f(s[nt][2] - mn1);
            float p3 = exp2f(s[nt][3] - mn1);
            rs0 += p0 + p1; rs1 += p2 + p3;
            int g = nt >> 1;
            if (nt & 1) {
                aP[g][2] = packh2(p0, p1);
                aP[g][3] = packh2(p2, p3);
            } else {
                aP[g][0] = packh2(p0, p1);
                aP[g][1] = packh2(p2, p3);
            }
        }
        rs0 += __shfl_xor_sync(0xffffffffu, rs0, 1);
        rs0 += __shfl_xor_sync(0xffffffffu, rs0, 2);
        rs1 += __shfl_xor_sync(0xffffffffu, rs1, 1);
        rs1 += __shfl_xor_sync(0xffffffffu, rs1, 2);
        l0 = l0*al0 + rs0;  l1 = l1*al1 + rs1;
        m0 = mn0;           m1 = mn1;

        if (__ballot_sync(0xffffffffu, (al0 != 1.f) | (al1 != 1.f))) {
            #pragma unroll
            for (int nt = 0; nt < 16; nt++) {
                o[nt][0] *= al0; o[nt][1] *= al0;
                o[nt][2] *= al1; o[nt][3] *= al1;
            }
        }

        cpwait<0>();
        __syncthreads();

        if (kt + 1 < nkt) LOAD_K(kt + 1);

        #pragma unroll
        for (int g4 = 0; g4 < 8; g4++) {
            #pragma unroll
            for (int vg = 0; vg < 8; vg++) {
                unsigned bv[4];
                ldsm4t(bv, &sh[VS_OFF + (g4*16 + lidx)*VST + vg*16 + lhi]);
                mma16(o[vg*2],     aP[g4], bv[0], bv[1]);
                mma16(o[vg*2 + 1], aP[g4], bv[2], bv[3]);
            }
        }

        if (kt + 1 < nkt) {
            __syncthreads();
            LOAD_V(kt + 1);
        }
    }

    float inv0 = 1.f / l0, inv1 = 1.f / l1;
    __half* Ob = O + (size_t)(b*SEQ + q0)*QDIM + h*128;
    #pragma unroll
    for (int nt = 0; nt < 16; nt++) {
        int col = nt*8 + lr*2;
        *(__half2*)&Ob[(size_t) mrow     *QDIM + col] =
            __floats2half2_rn(o[nt][0]*inv0, o[nt][1]*inv0);
        *(__half2*)&Ob[(size_t)(mrow + 8)*QDIM + col] =
            __floats2half2_rn(o[nt][2]*inv1, o[nt][3]*inv1);
    }
    #undef LOAD_K
    #undef LOAD_V
}

// ---------------- launch ---------------------------------------------------
extern "C" void kernel_launch(void* const* d_in, const int* in_sizes, int n_in,
                              void* d_out, int out_size)
{
    const float* x  = (const float*)d_in[0];
    const float* Wq = (const float*)d_in[1];
    const float* Wk = (const float*)d_in[2];
    const float* Wv = (const float*)d_in[3];
    const float* Wo = (const float*)d_in[4];
    float* out = (float*)d_out;

    __half *xh, *wqh, *wkh, *wvh, *woh, *qh, *kh, *vh, *ah;
    cudaGetSymbolAddress((void**)&xh,  g_xh);
    cudaGetSymbolAddress((void**)&wqh, g_wqh);
    cudaGetSymbolAddress((void**)&wkh, g_wkh);
    cudaGetSymbolAddress((void**)&wvh, g_wvh);
    cudaGetSymbolAddress((void**)&woh, g_woh);
    cudaGetSymbolAddress((void**)&qh,  g_qh);
    cudaGetSymbolAddress((void**)&kh,  g_kh);
    cudaGetSymbolAddress((void**)&vh,  g_vh);
    cudaGetSymbolAddress((void**)&ah,  g_ah);

    rope_table_kernel<<<(SEQ*64 + 255)/256, 256>>>();

    f2h_all<<<F2H_TOT, 256>>>((const float4*)x,  (__half2*)xh,
                              (const float4*)Wq, (__half2*)wqh,
                              (const float4*)Wk, (__half2*)wkh,
                              (const float4*)Wv, (__half2*)wvh,
                              (const float4*)Wo, (__half2*)woh);

    cudaFuncSetAttribute(proj_qkv, cudaFuncAttributeMaxDynamicSharedMemorySize,
                         GSMEM);
    proj_qkv<<<dim3(24, ROWS/128), 256, GSMEM>>>(xh, wqh, wkh, wvh, qh, kh, vh);

    cudaFuncSetAttribute(flash_f16, cudaFuncAttributeMaxDynamicSharedMemorySize,
                         FLASH_SMEM);
    flash_f16<<<dim3(SEQ/64, NH, BATCH), 128, FLASH_SMEM>>>(qh, kh, vh, ah);

    cudaFuncSetAttribute(gemm_f16_f32out, cudaFuncAttributeMaxDynamicSharedMemorySize,
                         GSMEM);
    gemm_f16_f32out<<<dim3(QDIM/128, ROWS/128), 256, GSMEM>>>(ah, woh, out, ROWS, QDIM, HIDDEN);
}

// round 16
// speedup vs baseline: 1.0271x; 1.0074x over previous
#include <cuda_runtime.h>
#include <cuda_fp16.h>
#include <cstdint>
#include <math.h>

#define SEQ    2048
#define BATCH  2
#define HIDDEN 2048
#define NH     16
#define NKV    4
#define HD     128
#define ROWS   (BATCH*SEQ)   /* 4096 */
#define QDIM   (NH*HD)       /* 2048 */
#define KVDIM  (NKV*HD)      /* 512  */

// ---------------- scratch (device globals: no allocation allowed) ----------
__device__ __half g_xh[ROWS*HIDDEN];    // 16 MB
__device__ __half g_wqh[HIDDEN*QDIM];   //  8 MB
__device__ __half g_wkh[HIDDEN*KVDIM];  //  2 MB
__device__ __half g_wvh[HIDDEN*KVDIM];  //  2 MB
__device__ __half g_woh[QDIM*HIDDEN];   //  8 MB
__device__ __half g_qh[ROWS*QDIM];      // 16 MB
__device__ __half g_kh[ROWS*KVDIM];     //  4 MB
__device__ __half g_vh[ROWS*KVDIM];     //  4 MB
__device__ __half g_ah[ROWS*QDIM];      // 16 MB
__device__ float  g_cos[SEQ*64];
__device__ float  g_sin[SEQ*64];

// ---------------- asm helpers ----------------------------------------------
__device__ __forceinline__ void ldsm4(unsigned* r, const void* p) {
    unsigned a = (unsigned)__cvta_generic_to_shared(p);
    asm volatile("ldmatrix.sync.aligned.m8n8.x4.shared.b16 {%0,%1,%2,%3}, [%4];"
        : "=r"(r[0]), "=r"(r[1]), "=r"(r[2]), "=r"(r[3]) : "r"(a));
}
__device__ __forceinline__ void ldsm4t(unsigned* r, const void* p) {
    unsigned a = (unsigned)__cvta_generic_to_shared(p);
    asm volatile("ldmatrix.sync.aligned.m8n8.x4.trans.shared.b16 {%0,%1,%2,%3}, [%4];"
        : "=r"(r[0]), "=r"(r[1]), "=r"(r[2]), "=r"(r[3]) : "r"(a));
}
__device__ __forceinline__ void mma16(float* d, const unsigned* a,
                                      unsigned b0, unsigned b1) {
    asm volatile("mma.sync.aligned.m16n8k16.row.col.f32.f16.f16.f32 "
        "{%0,%1,%2,%3}, {%4,%5,%6,%7}, {%8,%9}, {%0,%1,%2,%3};"
        : "+f"(d[0]), "+f"(d[1]), "+f"(d[2]), "+f"(d[3])
        : "r"(a[0]), "r"(a[1]), "r"(a[2]), "r"(a[3]), "r"(b0), "r"(b1));
}
__device__ __forceinline__ void cpa16(const void* smem, const void* g) {
    unsigned s = (unsigned)__cvta_generic_to_shared(smem);
    asm volatile("cp.async.cg.shared.global [%0], [%1], 16;" :: "r"(s), "l"(g));
}
__device__ __forceinline__ void cpcommit() { asm volatile("cp.async.commit_group;"); }
template<int N> __device__ __forceinline__ void cpwait() {
    asm volatile("cp.async.wait_group %0;" :: "n"(N));
}
__device__ __forceinline__ unsigned packh2(float x, float y) {
    unsigned r;
    asm("cvt.rn.f16x2.f32 %0, %1, %2;" : "=r"(r) : "f"(y), "f"(x));
    return r;
}

// ---------------- fused fp32 -> fp16 convert: 4 float4/thread (MLP=4) ------
// float4 counts: x 2097152, wq 1048576, wk 262144, wv 262144, wo 1048576
// per block: 256 thr * 4 = 1024 float4
#define F2H_BX  2048
#define F2H_BQ  (F2H_BX + 1024)    /* 3072 */
#define F2H_BK  (F2H_BQ + 256)     /* 3328 */
#define F2H_BV  (F2H_BK + 256)     /* 3584 */
#define F2H_TOT (F2H_BV + 1024)    /* 4608 */

__global__ void f2h_all(const float4* __restrict__ x,  __half2* __restrict__ xh,
                        const float4* __restrict__ wq, __half2* __restrict__ wqh,
                        const float4* __restrict__ wk, __half2* __restrict__ wkh,
                        const float4* __restrict__ wv, __half2* __restrict__ wvh,
                        const float4* __restrict__ wo, __half2* __restrict__ woh)
{
    int bx = blockIdx.x;
    const float4* src; __half2* dst; int base;
    if      (bx < F2H_BX) { src = x;  dst = xh;  base = 0; }
    else if (bx < F2H_BQ) { src = wq; dst = wqh; base = F2H_BX; }
    else if (bx < F2H_BK) { src = wk; dst = wkh; base = F2H_BQ; }
    else if (bx < F2H_BV) { src = wv; dst = wvh; base = F2H_BK; }
    else                  { src = wo; dst = woh; base = F2H_BV; }
    int i0 = (bx - base) * 1024 + threadIdx.x;
    float4 v0 = src[i0];
    float4 v1 = src[i0 + 256];
    float4 v2 = src[i0 + 512];
    float4 v3 = src[i0 + 768];
    dst[2*i0]             = __floats2half2_rn(v0.x, v0.y);
    dst[2*i0+1]           = __floats2half2_rn(v0.z, v0.w);
    dst[2*(i0+256)]       = __floats2half2_rn(v1.x, v1.y);
    dst[2*(i0+256)+1]     = __floats2half2_rn(v1.z, v1.w);
    dst[2*(i0+512)]       = __floats2half2_rn(v2.x, v2.y);
    dst[2*(i0+512)+1]     = __floats2half2_rn(v2.z, v2.w);
    dst[2*(i0+768)]       = __floats2half2_rn(v3.x, v3.y);
    dst[2*(i0+768)+1]     = __floats2half2_rn(v3.z, v3.w);
}

// ---------------- RoPE table (no fp64 transcendentals) ---------------------
__global__ void rope_table_kernel() {
    int i = blockIdx.x * blockDim.x + threadIdx.x;
    if (i >= SEQ*64) return;
    int s = i >> 6, d = i & 63;
    double base_pow[6] = { 8.6596432336006535e-1, 7.4989420933245583e-1,
                           5.6234132519034908e-1, 3.1622776601683794e-1,
                           1.0e-1, 1.0e-2 };
    double invf = 1.0;
    #pragma unroll
    for (int b = 0; b < 6; b++)
        if (d & (1 << b)) invf *= base_pow[b];
    double ang = (double)s * invf;
    const double TWO_PI_HI = 6.2831853071795862e+0;
    const double TWO_PI_LO = 2.4492935982947064e-16;
    double k = rint(ang * 1.5915494309189533e-1);
    double r = fma(-k, TWO_PI_HI, ang);
    r = fma(-k, TWO_PI_LO, r);
    float sn, cs;
    sincosf((float)r, &sn, &cs);
    g_cos[i] = cs;
    g_sin[i] = sn;
}

// ---------------- GEMM tiles: 128x128, BK=64, 2-stage, 256 thr -------------
#define AST2 72     /* A row stride in halves (144 B; 36 words ≡ 4 mod 32) */
#define BST  136    /* B row stride in halves */
#define CST  136
#define ASTAGE (128*AST2)          /* 9216 halves  */
#define BSTAGE (64*BST)            /* 8704 halves  */
#define GSMEM  ((2*ASTAGE + 2*BSTAGE)*2)   /* 71680 bytes */

#define G_LOAD_STAGE(As, Bs, buf, k0, Ab, ldA, Bb, ldB) do {                   \
    _Pragma("unroll")                                                          \
    for (int i_ = 0; i_ < 4; i_++) {                                           \
        int c_ = tid + i_*256;                                                 \
        int m_ = c_ >> 3, kc_ = (c_ & 7) * 8;                                  \
        cpa16(&As[(buf)*ASTAGE + m_*AST2 + kc_],                               \
              Ab + (size_t)m_*(ldA) + (k0) + kc_);                             \
    }                                                                          \
    _Pragma("unroll")                                                          \
    for (int i_ = 0; i_ < 4; i_++) {                                           \
        int c_ = tid + i_*256;                                                 \
        int k_ = c_ >> 4, nc_ = (c_ & 15) * 8;                                 \
        cpa16(&Bs[(buf)*BSTAGE + k_*BST + nc_],                                \
              Bb + (size_t)((k0)+k_)*(ldB) + nc_);                             \
    }                                                                          \
    cpcommit();                                                                \
} while (0)

#define G_COMPUTE(As, Bs, buf) do {                                            \
    _Pragma("unroll")                                                          \
    for (int kk = 0; kk < 64; kk += 16) {                                      \
        unsigned a_[4][4], b_[2][4];                                           \
        _Pragma("unroll")                                                      \
        for (int mt = 0; mt < 4; mt++) {                                       \
            int m0 = wm*64 + mt*16;                                            \
            ldsm4(a_[mt], &As[(buf)*ASTAGE + (m0 + (l & 15))*AST2 + kk         \
                               + ((l >> 4) << 3)]);                            \
        }                                                                      \
        _Pragma("unroll")                                                      \
        for (int g = 0; g < 2; g++) {                                          \
            int n0 = wn*32 + g*16;                                             \
            ldsm4t(b_[g], &Bs[(buf)*BSTAGE + (kk + (l & 15))*BST + n0          \
                               + ((l >> 4) << 3)]);                            \
        }                                                                      \
        _Pragma("unroll")                                                      \
        for (int mt = 0; mt < 4; mt++)                                         \
            _Pragma("unroll")                                                  \
            for (int nt = 0; nt < 4; nt++) {                                   \
                const unsigned* bg = b_[nt >> 1];                              \
                if (nt & 1) mma16(acc[mt][nt], a_[mt], bg[2], bg[3]);          \
                else        mma16(acc[mt][nt], a_[mt], bg[0], bg[1]);          \
            }                                                                  \
    }                                                                          \
} while (0)

// ---------------- fused QKV projection + RoPE ------------------------------
__global__ __launch_bounds__(256, 2) void proj_qkv(
    const __half* __restrict__ A,
    const __half* __restrict__ Wq, const __half* __restrict__ Wk,
    const __half* __restrict__ Wv,
    __half* __restrict__ Qo, __half* __restrict__ Ko, __half* __restrict__ Vo)
{
    extern __shared__ __half psm[];
    __half* As = psm;                       // [2][ASTAGE]
    __half* Bs = psm + 2*ASTAGE;            // [2][BSTAGE]
    __half* Cs = psm;                       // [128*CST] epilogue alias

    const int tid  = threadIdx.x;
    const int l    = tid & 31, warp = tid >> 5;
    const int wm = warp >> 2, wn = warp & 3;
    const int bx = blockIdx.x, by = blockIdx.y;
    const int lq = l >> 2, lr = l & 3;

    const __half* Bb; __half* Cb; int ldB; bool rope;
    if (bx < 16)      { Bb = Wq + bx*128;      ldB = QDIM;  Cb = Qo + bx*128;      rope = true; }
    else if (bx < 20) { Bb = Wk + (bx-16)*128; ldB = KVDIM; Cb = Ko + (bx-16)*128; rope = true; }
    else              { Bb = Wv + (bx-20)*128; ldB = KVDIM; Cb = Vo + (bx-20)*128; rope = false; }

    const __half* Ab = A + (size_t)(by*128)*HIDDEN;

    float acc[4][4][4];
    #pragma unroll
    for (int i = 0; i < 4; i++)
        #pragma unroll
        for (int j = 0; j < 4; j++)
            #pragma unroll
            for (int t = 0; t < 4; t++) acc[i][j][t] = 0.f;

    G_LOAD_STAGE(As, Bs, 0, 0, Ab, HIDDEN, Bb, ldB);

    const int nIter = HIDDEN / 64;   // 32
    for (int it = 0; it < nIter; it++) {
        int buf = it & 1;
        if (it + 1 < nIter) {
            G_LOAD_STAGE(As, Bs, buf ^ 1, (it+1)*64, Ab, HIDDEN, Bb, ldB);
            cpwait<1>();
        } else cpwait<0>();
        __syncthreads();
        G_COMPUTE(As, Bs, buf);
        __syncthreads();
    }

    if (!rope) {
        #pragma unroll
        for (int mt = 0; mt < 4; mt++) {
            int row = by*128 + wm*64 + mt*16 + lq;
            #pragma unroll
            for (int nt = 0; nt < 4; nt++) {
                int col = wn*32 + nt*8 + lr*2;
                *(__half2*)&Cb[(size_t) row     *KVDIM + col] =
                    __floats2half2_rn(acc[mt][nt][0], acc[mt][nt][1]);
                *(__half2*)&Cb[(size_t)(row + 8)*KVDIM + col] =
                    __floats2half2_rn(acc[mt][nt][2], acc[mt][nt][3]);
            }
        }
        return;
    }

    const int ldC = (bx < 16) ? QDIM : KVDIM;
    #pragma unroll
    for (int mt = 0; mt < 4; mt++) {
        int row = wm*64 + mt*16 + lq;
        #pragma unroll
        for (int nt = 0; nt < 4; nt++) {
            int col = wn*32 + nt*8 + lr*2;
            *(__half2*)&Cs[ row     *CST + col] =
                __floats2half2_rn(acc[mt][nt][0], acc[mt][nt][1]);
            *(__half2*)&Cs[(row + 8)*CST + col] =
                __floats2half2_rn(acc[mt][nt][2], acc[mt][nt][3]);
        }
    }
    __syncthreads();

    #pragma unroll
    for (int i = 0; i < 32; i++) {
        int e   = tid + i*256;
        int row = e >> 6;
        int c2  = (e & 63) * 2;
        int d   = c2 & 63;
        float2 x1 = __half22float2(*(__half2*)&Cs[row*CST + c2]);
        float2 x2 = __half22float2(*(__half2*)&Cs[row*CST + (c2 ^ 64)]);
        int sp = (by*128 + row) & (SEQ - 1);
        float c0 = g_cos[sp*64 + d],     s0 = g_sin[sp*64 + d];
        float c1 = g_cos[sp*64 + d + 1], s1 = g_sin[sp*64 + d + 1];
        float r0, r1;
        if (c2 < 64) { r0 = x1.x*c0 - x2.x*s0; r1 = x1.y*c1 - x2.y*s1; }
        else         { r0 = x1.x*c0 + x2.x*s0; r1 = x1.y*c1 + x2.y*s1; }
        *(__half2*)&Cb[(size_t)(by*128 + row)*ldC + c2] = __floats2half2_rn(r0, r1);
    }
}

// ---------------- Wo GEMM (fp32 out) ---------------------------------------
__global__ __launch_bounds__(256, 2) void gemm_f16_f32out(
    const __half* __restrict__ A, const __half* __restrict__ B,
    float* __restrict__ C, int M, int N, int K)
{
    extern __shared__ __half gsm[];
    __half* As = gsm;
    __half* Bs = gsm + 2*ASTAGE;

    const int tid  = threadIdx.x;
    const int l    = tid & 31, warp = tid >> 5;
    const int wm = warp >> 2, wn = warp & 3;
    const int bx = blockIdx.x, by = blockIdx.y;
    const int lq = l >> 2, lr = l & 3;

    const __half* Ab = A + (size_t)(by*128)*K;
    const __half* Bb = B + (size_t)bx*128;

    float acc[4][4][4];
    #pragma unroll
    for (int i = 0; i < 4; i++)
        #pragma unroll
        for (int j = 0; j < 4; j++)
            #pragma unroll
            for (int t = 0; t < 4; t++) acc[i][j][t] = 0.f;

    G_LOAD_STAGE(As, Bs, 0, 0, Ab, K, Bb, N);

    const int nIter = K / 64;
    for (int it = 0; it < nIter; it++) {
        int buf = it & 1;
        if (it + 1 < nIter) {
            G_LOAD_STAGE(As, Bs, buf ^ 1, (it+1)*64, Ab, K, Bb, N);
            cpwait<1>();
        } else cpwait<0>();
        __syncthreads();
        G_COMPUTE(As, Bs, buf);
        __syncthreads();
    }

    #pragma unroll
    for (int mt = 0; mt < 4; mt++) {
        int row = by*128 + wm*64 + mt*16 + lq;
        #pragma unroll
        for (int nt = 0; nt < 4; nt++) {
            int col = bx*128 + wn*32 + nt*8 + lr*2;
            *(float2*)&C[(size_t) row     *N + col] =
                make_float2(acc[mt][nt][0], acc[mt][nt][1]);
            *(float2*)&C[(size_t)(row + 8)*N + col] =
                make_float2(acc[mt][nt][2], acc[mt][nt][3]);
        }
    }
}

// ---------------- flash attention: BM=64, BN=128, P in regs (R10) ----------
#define QST 136
#define KST 136
#define VST 136
#define QS_OFF 0
#define KS_OFF (64*QST)                /* 8704  */
#define VS_OFF (KS_OFF + 128*KST)      /* 26112 */
#define FLASH_SMEM ((VS_OFF + 128*VST)*2)   /* 87040 bytes */

__global__ __launch_bounds__(128, 2) void flash_f16(
    const __half* __restrict__ Q, const __half* __restrict__ K,
    const __half* __restrict__ V, __half* __restrict__ O)
{
    extern __shared__ __half sh[];
    const int tid  = threadIdx.x;
    const int l    = tid & 31, w = tid >> 5;
    const int lq = l >> 2, lr = l & 3;
    const int qt = (gridDim.x - 1) - blockIdx.x;   // heavy tiles first
    const int h  = blockIdx.y, b = blockIdx.z;
    const int hk = h >> 2;
    const int q0 = qt * 64;
    const float sc2 = 0.08838834764831845f * 1.4426950408889634f;

    const __half* Qbase = Q + (size_t)(b*SEQ + q0)*QDIM + h*128;
    const __half* Kb0   = K + (size_t)(b*SEQ)*KVDIM + hk*128;
    const __half* Vb0   = V + (size_t)(b*SEQ)*KVDIM + hk*128;

    #pragma unroll
    for (int i = 0; i < 8; i++) {
        int c = tid + i*128;
        int m = c >> 4, kc = (c & 15) * 8;
        cpa16(&sh[QS_OFF + m*QST + kc], Qbase + (size_t)m*QDIM + kc);
    }
    cpcommit();

    #define LOAD_K(kt) do {                                                    \
        const __half* kb = Kb0 + (size_t)(kt)*128*KVDIM;                       \
        _Pragma("unroll")                                                      \
        for (int i = 0; i < 16; i++) {                                         \
            int c = tid + i*128;                                               \
            int r = c >> 4, kc = (c & 15) * 8;                                 \
            cpa16(&sh[KS_OFF + r*KST + kc], kb + (size_t)r*KVDIM + kc);        \
        }                                                                      \
        cpcommit();                                                            \
    } while (0)
    #define LOAD_V(kt) do {                                                    \
        const __half* vb = Vb0 + (size_t)(kt)*128*KVDIM;                       \
        _Pragma("unroll")                                                      \
        for (int i = 0; i < 16; i++) {                                         \
            int c = tid + i*128;                                               \
            int r = c >> 4, kc = (c & 15) * 8;                                 \
            cpa16(&sh[VS_OFF + r*VST + kc], vb + (size_t)r*KVDIM + kc);        \
        }                                                                      \
        cpcommit();                                                            \
    } while (0)

    LOAD_K(0);
    LOAD_V(0);

    float o[16][4];
    #pragma unroll
    for (int nt = 0; nt < 16; nt++)
        #pragma unroll
        for (int t = 0; t < 4; t++) o[nt][t] = 0.f;
    float m0 = -INFINITY, m1 = -INFINITY, l0 = 0.f, l1 = 0.f;

    const int nkt  = qt/2 + 1;
    const int mrow = w*16 + lq;
    const int lidx = l & 15, lhi = (l >> 4) << 3;

    for (int kt = 0; kt < nkt; kt++) {
        cpwait<1>();
        __syncthreads();

        float s[16][4];
        #pragma unroll
        for (int nt = 0; nt < 16; nt++)
            #pragma unroll
            for (int t = 0; t < 4; t++) s[nt][t] = 0.f;

        #pragma unroll
        for (int kk = 0; kk < 128; kk += 16) {
            unsigned a[4];
            ldsm4(a, &sh[QS_OFF + (w*16 + lidx)*QST + kk + lhi]);
            #pragma unroll
            for (int g = 0; g < 8; g++) {
                unsigned bk[4];
                int n0 = g*16;
                ldsm4(bk, &sh[KS_OFF + (n0 + ((l >> 4) << 3) + (l & 7))*KST
                               + kk + (((l >> 3) & 1) << 3)]);
                mma16(s[g*2],     a, bk[0], bk[1]);
                mma16(s[g*2 + 1], a, bk[2], bk[3]);
            }
        }

        const int r0 = q0 + mrow, r1 = r0 + 8;
        const bool need_mask = (kt == nkt - 1);
        #pragma unroll
        for (int nt = 0; nt < 16; nt++) {
            int col = kt*128 + nt*8 + lr*2;
            s[nt][0] *= sc2; s[nt][1] *= sc2;
            s[nt][2] *= sc2; s[nt][3] *= sc2;
            if (need_mask) {
                if (col     > r0) s[nt][0] = -INFINITY;
                if (col + 1 > r0) s[nt][1] = -INFINITY;
                if (col     > r1) s[nt][2] = -INFINITY;
                if (col + 1 > r1) s[nt][3] = -INFINITY;
            }
        }

        float mx0 = -INFINITY, mx1 = -INFINITY;
        #pragma unroll
        for (int nt = 0; nt < 16; nt++) {
            mx0 = fmaxf(mx0, fmaxf(s[nt][0], s[nt][1]));
            mx1 = fmaxf(mx1, fmaxf(s[nt][2], s[nt][3]));
        }
        mx0 = fmaxf(mx0, __shfl_xor_sync(0xffffffffu, mx0, 1));
        mx0 = fmaxf(mx0, __shfl_xor_sync(0xffffffffu, mx0, 2));
        mx1 = fmaxf(mx1, __shfl_xor_sync(0xffffffffu, mx1, 1));
        mx1 = fmaxf(mx1, __shfl_xor_sync(0xffffffffu, mx1, 2));
        float mn0 = fmaxf(m0, mx0), mn1 = fmaxf(m1, mx1);
        float al0 = exp2f(m0 - mn0), al1 = exp2f(m1 - mn1);

        unsigned aP[8][4];
        float rs0 = 0.f, rs1 = 0.f;
        #pragma unroll
        for (int nt = 0; nt < 16; nt++) {
            float p0 = exp2f(s[nt][0] - mn0);
            float p1 = exp2f(s[nt][1] - mn0);
            float p2 = exp2f(s[nt][2] - mn1);
            float p3 = exp2f(s[nt][3] - mn1);
            rs0 += p0 + p1; rs1 += p2 + p3;
            int g = nt >> 1;
            if (nt & 1) {
                aP[g][2] = packh2(p0, p1);
                aP[g][3] = packh2(p2, p3);
            } else {
                aP[g][0] = packh2(p0, p1);
                aP[g][1] = packh2(p2, p3);
            }
        }
        rs0 += __shfl_xor_sync(0xffffffffu, rs0, 1);
        rs0 += __shfl_xor_sync(0xffffffffu, rs0, 2);
        rs1 += __shfl_xor_sync(0xffffffffu, rs1, 1);
        rs1 += __shfl_xor_sync(0xffffffffu, rs1, 2);
        l0 = l0*al0 + rs0;  l1 = l1*al1 + rs1;
        m0 = mn0;           m1 = mn1;

        if (__ballot_sync(0xffffffffu, (al0 != 1.f) | (al1 != 1.f))) {
            #pragma unroll
            for (int nt = 0; nt < 16; nt++) {
                o[nt][0] *= al0; o[nt][1] *= al0;
                o[nt][2] *= al1; o[nt][3] *= al1;
            }
        }

        cpwait<0>();
        __syncthreads();

        if (kt + 1 < nkt) LOAD_K(kt + 1);

        #pragma unroll
        for (int g4 = 0; g4 < 8; g4++) {
            #pragma unroll
            for (int vg = 0; vg < 8; vg++) {
                unsigned bv[4];
                ldsm4t(bv, &sh[VS_OFF + (g4*16 + lidx)*VST + vg*16 + lhi]);
                mma16(o[vg*2],     aP[g4], bv[0], bv[1]);
                mma16(o[vg*2 + 1], aP[g4], bv[2], bv[3]);
            }
        }

        if (kt + 1 < nkt) {
            __syncthreads();
            LOAD_V(kt + 1);
        }
    }

    float inv0 = 1.f / l0, inv1 = 1.f / l1;
    __half* Ob = O + (size_t)(b*SEQ + q0)*QDIM + h*128;
    #pragma unroll
    for (int nt = 0; nt < 16; nt++) {
        int col = nt*8 + lr*2;
        *(__half2*)&Ob[(size_t) mrow     *QDIM + col] =
            __floats2half2_rn(o[nt][0]*inv0, o[nt][1]*inv0);
        *(__half2*)&Ob[(size_t)(mrow + 8)*QDIM + col] =
            __floats2half2_rn(o[nt][2]*inv1, o[nt][3]*inv1);
    }
    #undef LOAD_K
    #undef LOAD_V
}

// ---------------- launch ---------------------------------------------------
extern "C" void kernel_launch(void* const* d_in, const int* in_sizes, int n_in,
                              void* d_out, int out_size)
{
    const float* x  = (const float*)d_in[0];
    const float* Wq = (const float*)d_in[1];
    const float* Wk = (const float*)d_in[2];
    const float* Wv = (const float*)d_in[3];
    const float* Wo = (const float*)d_in[4];
    float* out = (float*)d_out;

    __half *xh, *wqh, *wkh, *wvh, *woh, *qh, *kh, *vh, *ah;
    cudaGetSymbolAddress((void**)&xh,  g_xh);
    cudaGetSymbolAddress((void**)&wqh, g_wqh);
    cudaGetSymbolAddress((void**)&wkh, g_wkh);
    cudaGetSymbolAddress((void**)&wvh, g_wvh);
    cudaGetSymbolAddress((void**)&woh, g_woh);
    cudaGetSymbolAddress((void**)&qh,  g_qh);
    cudaGetSymbolAddress((void**)&kh,  g_kh);
    cudaGetSymbolAddress((void**)&vh,  g_vh);
    cudaGetSymbolAddress((void**)&ah,  g_ah);

    rope_table_kernel<<<(SEQ*64 + 255)/256, 256>>>();

    f2h_all<<<F2H_TOT, 256>>>((const float4*)x,  (__half2*)xh,
                              (const float4*)Wq, (__half2*)wqh,
                              (const float4*)Wk, (__half2*)wkh,
                              (const float4*)Wv, (__half2*)wvh,
                              (const float4*)Wo, (__half2*)woh);

    cudaFuncSetAttribute(proj_qkv, cudaFuncAttributeMaxDynamicSharedMemorySize,
                         GSMEM);
    proj_qkv<<<dim3(24, ROWS/128), 256, GSMEM>>>(xh, wqh, wkh, wvh, qh, kh, vh);

    cudaFuncSetAttribute(flash_f16, cudaFuncAttributeMaxDynamicSharedMemorySize,
                         FLASH_SMEM);
    flash_f16<<<dim3(SEQ/64, NH, BATCH), 128, FLASH_SMEM>>>(qh, kh, vh, ah);

    cudaFuncSetAttribute(gemm_f16_f32out, cudaFuncAttributeMaxDynamicSharedMemorySize,
                         GSMEM);
    gemm_f16_f32out<<<dim3(QDIM/128, ROWS/128), 256, GSMEM>>>(ah, woh, out, ROWS, QDIM, HIDDEN);
}